// round 15
// baseline (speedup 1.0000x reference)
#include <cuda_runtime.h>
#include <cuda_fp16.h>
#include <math.h>

#define NN 100000
#define NE 800000
#define SCAN_T 1024
#define SCAN_NB ((NN + SCAN_T - 1) / SCAN_T)

// ------------------------- scratch (static device globals) -------------------
__device__ float  g_B1[(size_t)NN * 1152];   // layer1/3 out: [q|.|skip|P] ld=640/1152
__device__ float  g_B2[(size_t)NN * 640];    // layer2 out
__device__ __half g_KV[(size_t)NN * 512];    // compact fp16 k|v per node (2C halfs)
__device__ float  g_Wp[442368];              // packed weights, 3 slots
__device__ float  g_bp[3840];                // packed bias, 3 slots of 1280
__device__ int    g_cnt[NN];
__device__ int    g_off[NN + 1];
__device__ int    g_bsum[SCAN_NB + 1];
__device__ int    g_cursor[NN];
__device__ int    g_srcS[NE];
__device__ float  g_attrS[(size_t)NE * 16];

// ------------------------- helpers ------------------------------------------
__device__ __forceinline__ unsigned tf32(float x) {
    unsigned u;
    asm("cvt.rna.tf32.f32 %0, %1;" : "=r"(u) : "f"(x));
    return u;
}

__device__ __forceinline__ void mma_tf32(float* c, const unsigned* a, const unsigned* b) {
    asm volatile(
        "mma.sync.aligned.m16n8k8.row.col.f32.tf32.tf32.f32 "
        "{%0,%1,%2,%3}, {%4,%5,%6,%7}, {%8,%9}, {%0,%1,%2,%3};"
        : "+f"(c[0]), "+f"(c[1]), "+f"(c[2]), "+f"(c[3])
        : "r"(a[0]), "r"(a[1]), "r"(a[2]), "r"(a[3]), "r"(b[0]), "r"(b[1]));
}

// ------------------------- weight packer -------------------------------------
// Wp columns: [0,C)=Wq [C,2C)=Wk [2C,3C)=Wv [3C,4C)=Wskip [4C,4C+16)=Wq@WeT, pad 0
__global__ void pack_k(const float* __restrict__ Wq, const float* __restrict__ Wk,
                       const float* __restrict__ Wv, const float* __restrict__ Ws,
                       const float* __restrict__ bq, const float* __restrict__ bk,
                       const float* __restrict__ bv, const float* __restrict__ bs,
                       const float* __restrict__ We,
                       float* __restrict__ Wp, float* __restrict__ bp,
                       int din, int C)
{
    const int Np = 4 * C + 128;
    const int Nq = 4 * C + 16;
    int total = din * Np;
    for (int idx = blockIdx.x * blockDim.x + threadIdx.x; idx < total;
         idx += gridDim.x * blockDim.x) {
        int k = idx / Np, j = idx - k * Np;
        float val = 0.f;
        if (j < 4 * C) {
            int sel = j / C, c = j - sel * C;
            const float* W = sel == 0 ? Wq : sel == 1 ? Wk : sel == 2 ? Wv : Ws;
            val = W[k * C + c];
        } else if (j < Nq) {
            int f = j - 4 * C;
            float acc = 0.f;
            for (int c = 0; c < C; c++) acc += Wq[k * C + c] * We[f * C + c];
            val = acc;
        }
        Wp[idx] = val;
        if (k == 0) {
            float bval = 0.f;
            if (j < 4 * C) {
                int sel = j / C, c = j - sel * C;
                const float* bb = sel == 0 ? bq : sel == 1 ? bk : sel == 2 ? bv : bs;
                bval = bb[c];
            } else if (j < Nq) {
                int f = j - 4 * C;
                float acc = 0.f;
                for (int c = 0; c < C; c++) acc += bq[c] * We[f * C + c];
                bval = acc;
            }
            bp[j] = bval;
        }
    }
}

// ------------------------- sort: histogram / scan / scatter ------------------
__global__ void zero_cnt_k(int* __restrict__ cnt, int n)
{
    int i = blockIdx.x * blockDim.x + threadIdx.x;
    if (i < n) cnt[i] = 0;
}

__global__ void hist_k(const int* __restrict__ dst, int* __restrict__ cnt, int nE)
{
    int e = blockIdx.x * blockDim.x + threadIdx.x;
    if (e < nE) atomicAdd(&cnt[dst[e]], 1);
}

__global__ void scan1_k(const int* __restrict__ cnt, int* __restrict__ off,
                        int* __restrict__ bsum, int n)
{
    __shared__ int s[SCAN_T];
    int gid = blockIdx.x * SCAN_T + threadIdx.x;
    int v = (gid < n) ? cnt[gid] : 0;
    s[threadIdx.x] = v;
    __syncthreads();
    for (int d = 1; d < SCAN_T; d <<= 1) {
        int t = (threadIdx.x >= d) ? s[threadIdx.x - d] : 0;
        __syncthreads();
        s[threadIdx.x] += t;
        __syncthreads();
    }
    if (gid < n) off[gid] = s[threadIdx.x] - v;
    if (threadIdx.x == SCAN_T - 1) bsum[blockIdx.x] = s[threadIdx.x];
}

__global__ void scan2_k(int* __restrict__ bsum, int nb)
{
    __shared__ int s[128];
    int v = (threadIdx.x < nb) ? bsum[threadIdx.x] : 0;
    s[threadIdx.x] = v;
    __syncthreads();
    for (int d = 1; d < 128; d <<= 1) {
        int t = (threadIdx.x >= d) ? s[threadIdx.x - d] : 0;
        __syncthreads();
        s[threadIdx.x] += t;
        __syncthreads();
    }
    if (threadIdx.x < nb) bsum[threadIdx.x] = s[threadIdx.x] - v;
}

__global__ void scan3_k(int* __restrict__ off, const int* __restrict__ bsum,
                        int* __restrict__ cursor, int n, int total)
{
    int gid = blockIdx.x * SCAN_T + threadIdx.x;
    if (gid < n) {
        int o = off[gid] + bsum[blockIdx.x];
        off[gid] = o;
        cursor[gid] = o;
    }
    if (gid == 0) off[n] = total;
}

__global__ void scatter_k(const int* __restrict__ src, const int* __restrict__ dst,
                          const float* __restrict__ attr, int* __restrict__ cursor,
                          int* __restrict__ srcS, float* __restrict__ attrS, int nE)
{
    int e = blockIdx.x * blockDim.x + threadIdx.x;
    if (e >= nE) return;
    int pos = atomicAdd(&cursor[dst[e]], 1);
    srcS[pos] = src[e];
    const float4* a4 = (const float4*)(attr + (size_t)e * 16);
    float4* o4 = (float4*)(attrS + (size_t)pos * 16);
    o4[0] = a4[0]; o4[1] = a4[1]; o4[2] = a4[2]; o4[3] = a4[3];
}

// ------------------------- TF32 tensor-core GEMM -----------------------------
__global__ __launch_bounds__(256, 2) void sgemm_tc_k(
    const float* __restrict__ A, int lda,
    const float* __restrict__ B, int ldb,
    const float* __restrict__ bias,
    float* __restrict__ Cmat, int ldc,
    __half* __restrict__ KV, int Ckv,
    int M, int K)
{
    __shared__ unsigned As[2][16][136];
    __shared__ unsigned Bs[2][16][136];

    const int t    = threadIdx.x;
    const int wid  = t >> 5;
    const int lane = t & 31;
    const int tg   = lane & 3;
    const int gi   = lane >> 2;
    const int wm   = (wid >> 2) * 64;
    const int wn   = (wid & 3) * 32;
    const int rowBase = blockIdx.x * 128;
    const int colBase = blockIdx.y * 128;

    const int ar = t >> 2;
    const int kc = (t & 3) * 4;
    const int kb = t >> 5;
    const int cb = (t & 31) * 4;

    float acc[4][4][4];
    #pragma unroll
    for (int mi = 0; mi < 4; mi++)
        #pragma unroll
        for (int ni = 0; ni < 4; ni++)
            #pragma unroll
            for (int c = 0; c < 4; c++) acc[mi][ni][c] = 0.f;

    const float4 z4 = make_float4(0.f, 0.f, 0.f, 0.f);
    float4 a0, a1, b0, b1;

    auto ldglob = [&](int kt) {
        int r0 = rowBase + ar, r1 = r0 + 64;
        a0 = (r0 < M) ? *(const float4*)(A + (size_t)r0 * lda + kt + kc) : z4;
        a1 = (r1 < M) ? *(const float4*)(A + (size_t)r1 * lda + kt + kc) : z4;
        b0 = *(const float4*)(B + (size_t)(kt + kb) * ldb + colBase + cb);
        b1 = *(const float4*)(B + (size_t)(kt + kb + 8) * ldb + colBase + cb);
    };
    auto stsh = [&](int buf) {
        As[buf][kc + 0][ar] = tf32(a0.x); As[buf][kc + 1][ar] = tf32(a0.y);
        As[buf][kc + 2][ar] = tf32(a0.z); As[buf][kc + 3][ar] = tf32(a0.w);
        As[buf][kc + 0][ar + 64] = tf32(a1.x); As[buf][kc + 1][ar + 64] = tf32(a1.y);
        As[buf][kc + 2][ar + 64] = tf32(a1.z); As[buf][kc + 3][ar + 64] = tf32(a1.w);
        Bs[buf][kb][cb + 0] = tf32(b0.x); Bs[buf][kb][cb + 1] = tf32(b0.y);
        Bs[buf][kb][cb + 2] = tf32(b0.z); Bs[buf][kb][cb + 3] = tf32(b0.w);
        Bs[buf][kb + 8][cb + 0] = tf32(b1.x); Bs[buf][kb + 8][cb + 1] = tf32(b1.y);
        Bs[buf][kb + 8][cb + 2] = tf32(b1.z); Bs[buf][kb + 8][cb + 3] = tf32(b1.w);
    };
    auto comp = [&](int buf) {
        #pragma unroll
        for (int k0 = 0; k0 < 16; k0 += 8) {
            unsigned af[4][4], bf[4][2];
            #pragma unroll
            for (int mi = 0; mi < 4; mi++) {
                int m0 = wm + mi * 16 + gi;
                af[mi][0] = As[buf][k0 + tg][m0];
                af[mi][1] = As[buf][k0 + tg][m0 + 8];
                af[mi][2] = As[buf][k0 + 4 + tg][m0];
                af[mi][3] = As[buf][k0 + 4 + tg][m0 + 8];
            }
            #pragma unroll
            for (int ni = 0; ni < 4; ni++) {
                int n0 = wn + ni * 8 + gi;
                bf[ni][0] = Bs[buf][k0 + tg][n0];
                bf[ni][1] = Bs[buf][k0 + 4 + tg][n0];
            }
            #pragma unroll
            for (int mi = 0; mi < 4; mi++)
                #pragma unroll
                for (int ni = 0; ni < 4; ni++)
                    mma_tf32(acc[mi][ni], af[mi], bf[ni]);
        }
    };

    ldglob(0);
    stsh(0);
    __syncthreads();
    int buf = 0;
    for (int kt = 16; kt < K; kt += 16) {
        ldglob(kt);
        comp(buf);
        stsh(buf ^ 1);
        __syncthreads();
        buf ^= 1;
    }
    comp(buf);

    const int Nreal = 4 * Ckv + 16;
    #pragma unroll
    for (int mi = 0; mi < 4; mi++) {
        int r0 = rowBase + wm + mi * 16 + gi;
        int r1 = r0 + 8;
        #pragma unroll
        for (int ni = 0; ni < 4; ni++) {
            int c = colBase + wn + ni * 8 + 2 * tg;
            if (c >= Nreal) continue;
            float2 bv = *(const float2*)(bias + c);
            bool inKV = (c >= Ckv) && (c < 3 * Ckv);
            float2 o0 = make_float2(acc[mi][ni][0] + bv.x, acc[mi][ni][1] + bv.y);
            float2 o1 = make_float2(acc[mi][ni][2] + bv.x, acc[mi][ni][3] + bv.y);
            if (inKV) {
                if (r0 < M)
                    *(__half2*)&KV[(size_t)r0 * (2 * Ckv) + (c - Ckv)] =
                        __floats2half2_rn(o0.x, o0.y);
                if (r1 < M)
                    *(__half2*)&KV[(size_t)r1 * (2 * Ckv) + (c - Ckv)] =
                        __floats2half2_rn(o1.x, o1.y);
            } else {
                if (r0 < M) *(float2*)&Cmat[(size_t)r0 * ldc + c] = o0;
                if (r1 < M) *(float2*)&Cmat[(size_t)r1 * ldc + c] = o1;
            }
        }
    }
}

// ------------------------- fused attention (no-max softmax) ------------------
// CLS: fuse final classifier into the epilogue (layer 3) — H never hits memory.
template <int C, bool RELU, bool CLS>
__global__ __launch_bounds__(256) void fused_attn_k(
    float* __restrict__ QKVS, int ld,
    const __half* __restrict__ KV,
    const float* __restrict__ attrS, const int* __restrict__ srcS,
    const int* __restrict__ off,
    const float* __restrict__ We, float isc, int n,
    const float* __restrict__ Wc, const float* __restrict__ bc,
    float* __restrict__ cls_out)
{
    constexpr int NV = C / 128;
    __shared__ float Ws[16 * C];
    __shared__ float Wcs[CLS ? 2560 : 1];
    __shared__ float bcs[CLS ? 10 : 1];
    for (int i = threadIdx.x; i < 16 * C; i += 256) Ws[i] = We[i];
    if (CLS) {
        for (int i = threadIdx.x; i < 2560; i += 256) Wcs[i] = Wc[i];
        if (threadIdx.x < 10) bcs[threadIdx.x] = bc[threadIdx.x];
    }
    __syncthreads();

    const int node = blockIdx.x * 8 + (threadIdx.x >> 5);
    const int lane = threadIdx.x & 31;
    if (node >= n) return;

    const int e0 = off[node], e1 = off[node + 1];

    float4 q[NV];
    const float4* qb = (const float4*)(QKVS + (size_t)node * ld);
    #pragma unroll
    for (int i = 0; i < NV; i++) q[i] = qb[lane + i * 32];

    const float pP = (lane < 16) ? QKVS[(size_t)node * ld + 4 * C + lane] : 0.f;

    float s = 0.f, tacc = 0.f;
    float4 vacc[NV];
    #pragma unroll
    for (int i = 0; i < NV; i++) vacc[i] = make_float4(0.f, 0.f, 0.f, 0.f);

    int pf_sn0 = 0, pf_sn1 = 0;
    float pf_av0 = 0.f, pf_av1 = 0.f;
    if (e0 < e1) {
        pf_sn0 = srcS[e0];
        pf_av0 = (lane < 16) ? __ldcs(&attrS[(size_t)e0 * 16 + lane]) : 0.f;
    }
    if (e0 + 1 < e1) {
        pf_sn1 = srcS[e0 + 1];
        pf_av1 = (lane < 16) ? __ldcs(&attrS[(size_t)(e0 + 1) * 16 + lane]) : 0.f;
    }

    int e = e0;
    while (e + 1 < e1) {
        const int sn0 = pf_sn0, sn1 = pf_sn1;
        const float av0 = pf_av0, av1 = pf_av1;
        if (e + 2 < e1) {
            pf_sn0 = srcS[e + 2];
            pf_av0 = (lane < 16) ? __ldcs(&attrS[(size_t)(e + 2) * 16 + lane]) : 0.f;
        }
        if (e + 3 < e1) {
            pf_sn1 = srcS[e + 3];
            pf_av1 = (lane < 16) ? __ldcs(&attrS[(size_t)(e + 3) * 16 + lane]) : 0.f;
        }

        const uint2* kv0 = (const uint2*)(KV + (size_t)sn0 * (2 * C));
        const uint2* kv1 = (const uint2*)(KV + (size_t)sn1 * (2 * C));

        uint2 ku0[NV], vu0[NV], ku1[NV], vu1[NV];
        #pragma unroll
        for (int i = 0; i < NV; i++) {
            ku0[i] = kv0[lane + i * 32];
            vu0[i] = kv0[C / 4 + lane + i * 32];
            ku1[i] = kv1[lane + i * 32];
            vu1[i] = kv1[C / 4 + lane + i * 32];
        }

        float p0 = av0 * pP, p1 = av1 * pP;
        #pragma unroll
        for (int i = 0; i < NV; i++) {
            float2 a0 = __half22float2(*(const __half2*)&ku0[i].x);
            float2 b0 = __half22float2(*(const __half2*)&ku0[i].y);
            float2 a1 = __half22float2(*(const __half2*)&ku1[i].x);
            float2 b1 = __half22float2(*(const __half2*)&ku1[i].y);
            p0 += q[i].x * a0.x + q[i].y * a0.y + q[i].z * b0.x + q[i].w * b0.y;
            p1 += q[i].x * a1.x + q[i].y * a1.y + q[i].z * b1.x + q[i].w * b1.y;
        }
        #pragma unroll
        for (int o = 16; o; o >>= 1) {
            p0 += __shfl_xor_sync(0xFFFFFFFFu, p0, o);
            p1 += __shfl_xor_sync(0xFFFFFFFFu, p1, o);
        }

        const float w0 = __expf(p0 * isc);
        const float w1 = __expf(p1 * isc);
        s += w0 + w1;
        tacc += w0 * av0 + w1 * av1;
        #pragma unroll
        for (int i = 0; i < NV; i++) {
            float2 a0 = __half22float2(*(const __half2*)&vu0[i].x);
            float2 b0 = __half22float2(*(const __half2*)&vu0[i].y);
            float2 a1 = __half22float2(*(const __half2*)&vu1[i].x);
            float2 b1 = __half22float2(*(const __half2*)&vu1[i].y);
            vacc[i].x += w0 * a0.x + w1 * a1.x;
            vacc[i].y += w0 * a0.y + w1 * a1.y;
            vacc[i].z += w0 * b0.x + w1 * b1.x;
            vacc[i].w += w0 * b0.y + w1 * b1.y;
        }
        e += 2;
    }

    if (e < e1) {
        const int sn = pf_sn0;
        const float av = pf_av0;
        const uint2* kv = (const uint2*)(KV + (size_t)sn * (2 * C));
        uint2 ku[NV], vu[NV];
        #pragma unroll
        for (int i = 0; i < NV; i++) {
            ku[i] = kv[lane + i * 32];
            vu[i] = kv[C / 4 + lane + i * 32];
        }

        float part = av * pP;
        #pragma unroll
        for (int i = 0; i < NV; i++) {
            float2 a = __half22float2(*(const __half2*)&ku[i].x);
            float2 b = __half22float2(*(const __half2*)&ku[i].y);
            part += q[i].x * a.x + q[i].y * a.y + q[i].z * b.x + q[i].w * b.y;
        }
        #pragma unroll
        for (int o = 16; o; o >>= 1) part += __shfl_xor_sync(0xFFFFFFFFu, part, o);

        const float p = __expf(part * isc);
        s += p;
        tacc += p * av;
        #pragma unroll
        for (int i = 0; i < NV; i++) {
            float2 a = __half22float2(*(const __half2*)&vu[i].x);
            float2 b = __half22float2(*(const __half2*)&vu[i].y);
            vacc[i].x += p * a.x;
            vacc[i].y += p * a.y;
            vacc[i].z += p * b.x;
            vacc[i].w += p * b.y;
        }
    }

    const float inv = 1.f / (s + 1e-16f);

    float4 ed[NV];
    #pragma unroll
    for (int i = 0; i < NV; i++) ed[i] = make_float4(0.f, 0.f, 0.f, 0.f);
    #pragma unroll
    for (int f = 0; f < 16; f++) {
        const float tf = __shfl_sync(0xFFFFFFFFu, tacc, f) * inv;
        #pragma unroll
        for (int i = 0; i < NV; i++) {
            float4 w = *(const float4*)&Ws[f * C + (lane + i * 32) * 4];
            ed[i].x += tf * w.x; ed[i].y += tf * w.y;
            ed[i].z += tf * w.z; ed[i].w += tf * w.w;
        }
    }

    float4* hb = (float4*)(QKVS + (size_t)node * ld + 3 * C);
    float ca[10];
    if (CLS) {
        #pragma unroll
        for (int c = 0; c < 10; c++) ca[c] = 0.f;
    }
    #pragma unroll
    for (int i = 0; i < NV; i++) {
        float4 sk = hb[lane + i * 32];
        float4 o;
        o.x = sk.x + vacc[i].x * inv + ed[i].x;
        o.y = sk.y + vacc[i].y * inv + ed[i].y;
        o.z = sk.z + vacc[i].z * inv + ed[i].z;
        o.w = sk.w + vacc[i].w * inv + ed[i].w;
        if (RELU) {
            o.x = fmaxf(o.x, 0.f); o.y = fmaxf(o.y, 0.f);
            o.z = fmaxf(o.z, 0.f); o.w = fmaxf(o.w, 0.f);
        }
        if (CLS) {
            const int cb = (lane + i * 32) * 4;
            #pragma unroll
            for (int c = 0; c < 10; c++) {
                ca[c] += o.x * Wcs[(cb + 0) * 10 + c]
                       + o.y * Wcs[(cb + 1) * 10 + c]
                       + o.z * Wcs[(cb + 2) * 10 + c]
                       + o.w * Wcs[(cb + 3) * 10 + c];
            }
        } else {
            hb[lane + i * 32] = o;
        }
    }

    if (CLS) {
        #pragma unroll
        for (int c = 0; c < 10; c++)
            #pragma unroll
            for (int o = 16; o; o >>= 1)
                ca[c] += __shfl_xor_sync(0xFFFFFFFFu, ca[c], o);
        if (lane == 0) {
            #pragma unroll
            for (int c = 0; c < 10; c++)
                cls_out[(size_t)node * 10 + c] = ca[c] + bcs[c];
        }
    }
}

// ------------------------- launch --------------------------------------------
extern "C" void kernel_launch(void* const* d_in, const int* in_sizes, int n_in,
                              void* d_out, int out_size)
{
    const float* x    = (const float*)d_in[0];
    const int*   ei   = (const int*)d_in[1];
    const float* attr = (const float*)d_in[2];
    const int* src = ei;
    const int* dst = ei + NE;

    float *B1, *B2, *Wp, *bp, *attrS;
    __half* KV;
    int *cnt, *off, *bsum, *cursor, *srcS;
    cudaGetSymbolAddress((void**)&B1,     g_B1);
    cudaGetSymbolAddress((void**)&B2,     g_B2);
    cudaGetSymbolAddress((void**)&KV,     g_KV);
    cudaGetSymbolAddress((void**)&Wp,     g_Wp);
    cudaGetSymbolAddress((void**)&bp,     g_bp);
    cudaGetSymbolAddress((void**)&cnt,    g_cnt);
    cudaGetSymbolAddress((void**)&off,    g_off);
    cudaGetSymbolAddress((void**)&bsum,   g_bsum);
    cudaGetSymbolAddress((void**)&cursor, g_cursor);
    cudaGetSymbolAddress((void**)&srcS,   g_srcS);
    cudaGetSymbolAddress((void**)&attrS,  g_attrS);

    auto IN = [&](int i) { return (const float*)d_in[i]; };

    static cudaStream_t sSide = nullptr;
    static cudaEvent_t  evFork = nullptr, evSide = nullptr;
    if (sSide == nullptr) {
        cudaStreamCreateWithFlags(&sSide, cudaStreamNonBlocking);
        cudaEventCreateWithFlags(&evFork, cudaEventDisableTiming);
        cudaEventCreateWithFlags(&evSide, cudaEventDisableTiming);
    }

    float* WpS[3] = { Wp, Wp + 147456, Wp + 294912 };
    float* bpS[3] = { bp, bp + 1280,   bp + 2560 };

    // ---- fork: side stream does edge sort + pack for layers 2,3 ----
    cudaEventRecord(evFork, 0);
    cudaStreamWaitEvent(sSide, evFork, 0);

    zero_cnt_k<<<(NN + 255) / 256, 256, 0, sSide>>>(cnt, NN);
    hist_k<<<(NE + 255) / 256, 256, 0, sSide>>>(dst, cnt, NE);
    scan1_k<<<SCAN_NB, SCAN_T, 0, sSide>>>(cnt, off, bsum, NN);
    scan2_k<<<1, 128, 0, sSide>>>(bsum, SCAN_NB);
    scan3_k<<<SCAN_NB, SCAN_T, 0, sSide>>>(off, bsum, cursor, NN, NE);
    scatter_k<<<(NE + 255) / 256, 256, 0, sSide>>>(src, dst, attr, cursor, srcS, attrS, NE);

    for (int l = 1; l < 3; l++) {
        const int base = 3 + l * 9;
        pack_k<<<256, 256, 0, sSide>>>(IN(base + 0), IN(base + 2), IN(base + 4),
                                       IN(base + 7), IN(base + 1), IN(base + 3),
                                       IN(base + 5), IN(base + 8), IN(base + 6),
                                       WpS[l], bpS[l], 128, l == 2 ? 256 : 128);
    }
    cudaEventRecord(evSide, sSide);

    // ---- main stream ----
    const float* Ain[3]  = { x, B1 + 3 * 128, B2 + 3 * 128 };
    int          lda[3]  = { 128, 640, 640 };
    int          Cc[3]   = { 128, 128, 256 };
    float*       outb[3] = { B1, B2, B1 };
    int          ldo[3]  = { 640, 640, 1152 };

    pack_k<<<256, 256>>>(IN(3), IN(5), IN(7), IN(10), IN(4), IN(6), IN(8), IN(11),
                         IN(9), WpS[0], bpS[0], 128, 128);

    bool joined = false;
    for (int l = 0; l < 3; l++) {
        const int C = Cc[l];
        float* out = outb[l];
        const int ld = ldo[l];

        dim3 gg((NN + 127) / 128, (4 * C + 128) / 128);
        sgemm_tc_k<<<gg, 256>>>(Ain[l], lda[l], WpS[l], 4 * C + 128, bpS[l],
                                out, ld, KV, C, NN, 128);

        if (!joined) {
            cudaStreamWaitEvent(0, evSide, 0);
            joined = true;
        }

        const float* We = IN(3 + l * 9 + 6);
        float isc = 1.0f / sqrtf((float)C);
        if (l == 0)
            fused_attn_k<128, true, false><<<(NN + 7) / 8, 256>>>(
                out, ld, KV, attrS, srcS, off, We, isc, NN, nullptr, nullptr, nullptr);
        else if (l == 1)
            fused_attn_k<128, true, false><<<(NN + 7) / 8, 256>>>(
                out, ld, KV, attrS, srcS, off, We, isc, NN, nullptr, nullptr, nullptr);
        else
            fused_attn_k<256, false, true><<<(NN + 7) / 8, 256>>>(
                out, ld, KV, attrS, srcS, off, We, isc, NN,
                IN(30), IN(31), (float*)d_out);
    }
}

// round 16
// speedup vs baseline: 1.4797x; 1.4797x over previous
#include <cuda_runtime.h>
#include <cuda_fp16.h>
#include <math.h>

#define NN 100000
#define NE 800000
#define SCAN_T 1024
#define SCAN_NB ((NN + SCAN_T - 1) / SCAN_T)

// ------------------------- scratch (static device globals) -------------------
__device__ float  g_B1[(size_t)NN * 1152];   // layer1/3 out: [q|.|skip|P] ld=640/1152
__device__ float  g_B2[(size_t)NN * 640];    // layer2 out
__device__ __half g_KV[(size_t)NN * 512];    // compact fp16 k|v per node (2C halfs)
__device__ float  g_Wp[442368];              // packed weights, 3 slots
__device__ float  g_bp[3840];                // packed bias, 3 slots of 1280
__device__ int    g_cnt[NN];
__device__ int    g_off[NN + 1];
__device__ int    g_bsum[SCAN_NB + 1];
__device__ int    g_cursor[NN];
__device__ int    g_srcS[NE];
__device__ float  g_attrS[(size_t)NE * 16];

// ------------------------- helpers ------------------------------------------
__device__ __forceinline__ unsigned tf32(float x) {
    unsigned u;
    asm("cvt.rna.tf32.f32 %0, %1;" : "=r"(u) : "f"(x));
    return u;
}

__device__ __forceinline__ void mma_tf32(float* c, const unsigned* a, const unsigned* b) {
    asm volatile(
        "mma.sync.aligned.m16n8k8.row.col.f32.tf32.tf32.f32 "
        "{%0,%1,%2,%3}, {%4,%5,%6,%7}, {%8,%9}, {%0,%1,%2,%3};"
        : "+f"(c[0]), "+f"(c[1]), "+f"(c[2]), "+f"(c[3])
        : "r"(a[0]), "r"(a[1]), "r"(a[2]), "r"(a[3]), "r"(b[0]), "r"(b[1]));
}

// ------------------------- weight packer -------------------------------------
// Wp columns: [0,C)=Wq [C,2C)=Wk [2C,3C)=Wv [3C,4C)=Wskip [4C,4C+16)=Wq@WeT, pad 0
__global__ void pack_k(const float* __restrict__ Wq, const float* __restrict__ Wk,
                       const float* __restrict__ Wv, const float* __restrict__ Ws,
                       const float* __restrict__ bq, const float* __restrict__ bk,
                       const float* __restrict__ bv, const float* __restrict__ bs,
                       const float* __restrict__ We,
                       float* __restrict__ Wp, float* __restrict__ bp,
                       int din, int C)
{
    const int Np = 4 * C + 128;
    const int Nq = 4 * C + 16;
    int total = din * Np;
    for (int idx = blockIdx.x * blockDim.x + threadIdx.x; idx < total;
         idx += gridDim.x * blockDim.x) {
        int k = idx / Np, j = idx - k * Np;
        float val = 0.f;
        if (j < 4 * C) {
            int sel = j / C, c = j - sel * C;
            const float* W = sel == 0 ? Wq : sel == 1 ? Wk : sel == 2 ? Wv : Ws;
            val = W[k * C + c];
        } else if (j < Nq) {
            int f = j - 4 * C;
            float acc = 0.f;
            for (int c = 0; c < C; c++) acc += Wq[k * C + c] * We[f * C + c];
            val = acc;
        }
        Wp[idx] = val;
        if (k == 0) {
            float bval = 0.f;
            if (j < 4 * C) {
                int sel = j / C, c = j - sel * C;
                const float* bb = sel == 0 ? bq : sel == 1 ? bk : sel == 2 ? bv : bs;
                bval = bb[c];
            } else if (j < Nq) {
                int f = j - 4 * C;
                float acc = 0.f;
                for (int c = 0; c < C; c++) acc += bq[c] * We[f * C + c];
                bval = acc;
            }
            bp[j] = bval;
        }
    }
}

// ------------------------- sort: histogram / scan / scatter ------------------
__global__ void zero_cnt_k(int* __restrict__ cnt, int n)
{
    int i = blockIdx.x * blockDim.x + threadIdx.x;
    if (i < n) cnt[i] = 0;
}

__global__ void hist_k(const int* __restrict__ dst, int* __restrict__ cnt, int nE)
{
    int e = blockIdx.x * blockDim.x + threadIdx.x;
    if (e < nE) atomicAdd(&cnt[dst[e]], 1);
}

__global__ void scan1_k(const int* __restrict__ cnt, int* __restrict__ off,
                        int* __restrict__ bsum, int n)
{
    __shared__ int s[SCAN_T];
    int gid = blockIdx.x * SCAN_T + threadIdx.x;
    int v = (gid < n) ? cnt[gid] : 0;
    s[threadIdx.x] = v;
    __syncthreads();
    for (int d = 1; d < SCAN_T; d <<= 1) {
        int t = (threadIdx.x >= d) ? s[threadIdx.x - d] : 0;
        __syncthreads();
        s[threadIdx.x] += t;
        __syncthreads();
    }
    if (gid < n) off[gid] = s[threadIdx.x] - v;
    if (threadIdx.x == SCAN_T - 1) bsum[blockIdx.x] = s[threadIdx.x];
}

__global__ void scan2_k(int* __restrict__ bsum, int nb)
{
    __shared__ int s[128];
    int v = (threadIdx.x < nb) ? bsum[threadIdx.x] : 0;
    s[threadIdx.x] = v;
    __syncthreads();
    for (int d = 1; d < 128; d <<= 1) {
        int t = (threadIdx.x >= d) ? s[threadIdx.x - d] : 0;
        __syncthreads();
        s[threadIdx.x] += t;
        __syncthreads();
    }
    if (threadIdx.x < nb) bsum[threadIdx.x] = s[threadIdx.x] - v;
}

__global__ void scan3_k(int* __restrict__ off, const int* __restrict__ bsum,
                        int* __restrict__ cursor, int n, int total)
{
    int gid = blockIdx.x * SCAN_T + threadIdx.x;
    if (gid < n) {
        int o = off[gid] + bsum[blockIdx.x];
        off[gid] = o;
        cursor[gid] = o;
    }
    if (gid == 0) off[n] = total;
}

__global__ void scatter_k(const int* __restrict__ src, const int* __restrict__ dst,
                          const float* __restrict__ attr, int* __restrict__ cursor,
                          int* __restrict__ srcS, float* __restrict__ attrS, int nE)
{
    int e = blockIdx.x * blockDim.x + threadIdx.x;
    if (e >= nE) return;
    int pos = atomicAdd(&cursor[dst[e]], 1);
    srcS[pos] = src[e];
    const float4* a4 = (const float4*)(attr + (size_t)e * 16);
    float4* o4 = (float4*)(attrS + (size_t)pos * 16);
    o4[0] = a4[0]; o4[1] = a4[1]; o4[2] = a4[2]; o4[3] = a4[3];
}

// ------------------------- TF32 tensor-core GEMM -----------------------------
__global__ __launch_bounds__(256, 2) void sgemm_tc_k(
    const float* __restrict__ A, int lda,
    const float* __restrict__ B, int ldb,
    const float* __restrict__ bias,
    float* __restrict__ Cmat, int ldc,
    __half* __restrict__ KV, int Ckv,
    int M, int K)
{
    __shared__ unsigned As[2][16][136];
    __shared__ unsigned Bs[2][16][136];

    const int t    = threadIdx.x;
    const int wid  = t >> 5;
    const int lane = t & 31;
    const int tg   = lane & 3;
    const int gi   = lane >> 2;
    const int wm   = (wid >> 2) * 64;
    const int wn   = (wid & 3) * 32;
    const int rowBase = blockIdx.x * 128;
    const int colBase = blockIdx.y * 128;

    const int ar = t >> 2;
    const int kc = (t & 3) * 4;
    const int kb = t >> 5;
    const int cb = (t & 31) * 4;

    float acc[4][4][4];
    #pragma unroll
    for (int mi = 0; mi < 4; mi++)
        #pragma unroll
        for (int ni = 0; ni < 4; ni++)
            #pragma unroll
            for (int c = 0; c < 4; c++) acc[mi][ni][c] = 0.f;

    const float4 z4 = make_float4(0.f, 0.f, 0.f, 0.f);
    float4 a0, a1, b0, b1;

    auto ldglob = [&](int kt) {
        int r0 = rowBase + ar, r1 = r0 + 64;
        a0 = (r0 < M) ? *(const float4*)(A + (size_t)r0 * lda + kt + kc) : z4;
        a1 = (r1 < M) ? *(const float4*)(A + (size_t)r1 * lda + kt + kc) : z4;
        b0 = *(const float4*)(B + (size_t)(kt + kb) * ldb + colBase + cb);
        b1 = *(const float4*)(B + (size_t)(kt + kb + 8) * ldb + colBase + cb);
    };
    auto stsh = [&](int buf) {
        As[buf][kc + 0][ar] = tf32(a0.x); As[buf][kc + 1][ar] = tf32(a0.y);
        As[buf][kc + 2][ar] = tf32(a0.z); As[buf][kc + 3][ar] = tf32(a0.w);
        As[buf][kc + 0][ar + 64] = tf32(a1.x); As[buf][kc + 1][ar + 64] = tf32(a1.y);
        As[buf][kc + 2][ar + 64] = tf32(a1.z); As[buf][kc + 3][ar + 64] = tf32(a1.w);
        Bs[buf][kb][cb + 0] = tf32(b0.x); Bs[buf][kb][cb + 1] = tf32(b0.y);
        Bs[buf][kb][cb + 2] = tf32(b0.z); Bs[buf][kb][cb + 3] = tf32(b0.w);
        Bs[buf][kb + 8][cb + 0] = tf32(b1.x); Bs[buf][kb + 8][cb + 1] = tf32(b1.y);
        Bs[buf][kb + 8][cb + 2] = tf32(b1.z); Bs[buf][kb + 8][cb + 3] = tf32(b1.w);
    };
    auto comp = [&](int buf) {
        #pragma unroll
        for (int k0 = 0; k0 < 16; k0 += 8) {
            unsigned af[4][4], bf[4][2];
            #pragma unroll
            for (int mi = 0; mi < 4; mi++) {
                int m0 = wm + mi * 16 + gi;
                af[mi][0] = As[buf][k0 + tg][m0];
                af[mi][1] = As[buf][k0 + tg][m0 + 8];
                af[mi][2] = As[buf][k0 + 4 + tg][m0];
                af[mi][3] = As[buf][k0 + 4 + tg][m0 + 8];
            }
            #pragma unroll
            for (int ni = 0; ni < 4; ni++) {
                int n0 = wn + ni * 8 + gi;
                bf[ni][0] = Bs[buf][k0 + tg][n0];
                bf[ni][1] = Bs[buf][k0 + 4 + tg][n0];
            }
            #pragma unroll
            for (int mi = 0; mi < 4; mi++)
                #pragma unroll
                for (int ni = 0; ni < 4; ni++)
                    mma_tf32(acc[mi][ni], af[mi], bf[ni]);
        }
    };

    ldglob(0);
    stsh(0);
    __syncthreads();
    int buf = 0;
    for (int kt = 16; kt < K; kt += 16) {
        ldglob(kt);
        comp(buf);
        stsh(buf ^ 1);
        __syncthreads();
        buf ^= 1;
    }
    comp(buf);

    const int Nreal = 4 * Ckv + 16;
    #pragma unroll
    for (int mi = 0; mi < 4; mi++) {
        int r0 = rowBase + wm + mi * 16 + gi;
        int r1 = r0 + 8;
        #pragma unroll
        for (int ni = 0; ni < 4; ni++) {
            int c = colBase + wn + ni * 8 + 2 * tg;
            if (c >= Nreal) continue;
            float2 bv = *(const float2*)(bias + c);
            bool inKV = (c >= Ckv) && (c < 3 * Ckv);
            float2 o0 = make_float2(acc[mi][ni][0] + bv.x, acc[mi][ni][1] + bv.y);
            float2 o1 = make_float2(acc[mi][ni][2] + bv.x, acc[mi][ni][3] + bv.y);
            if (inKV) {
                if (r0 < M)
                    *(__half2*)&KV[(size_t)r0 * (2 * Ckv) + (c - Ckv)] =
                        __floats2half2_rn(o0.x, o0.y);
                if (r1 < M)
                    *(__half2*)&KV[(size_t)r1 * (2 * Ckv) + (c - Ckv)] =
                        __floats2half2_rn(o1.x, o1.y);
            } else {
                if (r0 < M) *(float2*)&Cmat[(size_t)r0 * ldc + c] = o0;
                if (r1 < M) *(float2*)&Cmat[(size_t)r1 * ldc + c] = o1;
            }
        }
    }
}

// ------------------------- fused attention (no-max softmax, warp-strided) ----
// Each warp processes multiple nodes (grid-stride over warps): averages the
// Poisson degree distribution within a warp, removing the per-block max-degree
// tail that warp-per-node suffered. Per-node body identical to the R12 kernel.
template <int C, bool RELU>
__global__ __launch_bounds__(256) void fused_attn_k(
    float* __restrict__ QKVS, int ld,
    const __half* __restrict__ KV,
    const float* __restrict__ attrS, const int* __restrict__ srcS,
    const int* __restrict__ off,
    const float* __restrict__ We, float isc, int n)
{
    constexpr int NV = C / 128;
    __shared__ float Ws[16 * C];
    for (int i = threadIdx.x; i < 16 * C; i += 256) Ws[i] = We[i];
    __syncthreads();

    const int lane  = threadIdx.x & 31;
    const int warp0 = blockIdx.x * 8 + (threadIdx.x >> 5);
    const int nwarp = gridDim.x * 8;

    for (int node = warp0; node < n; node += nwarp) {

        const int e0 = off[node], e1 = off[node + 1];

        float4 q[NV];
        const float4* qb = (const float4*)(QKVS + (size_t)node * ld);
        #pragma unroll
        for (int i = 0; i < NV; i++) q[i] = qb[lane + i * 32];

        const float pP = (lane < 16) ? QKVS[(size_t)node * ld + 4 * C + lane] : 0.f;

        float s = 0.f, tacc = 0.f;
        float4 vacc[NV];
        #pragma unroll
        for (int i = 0; i < NV; i++) vacc[i] = make_float4(0.f, 0.f, 0.f, 0.f);

        int pf_sn0 = 0, pf_sn1 = 0;
        float pf_av0 = 0.f, pf_av1 = 0.f;
        if (e0 < e1) {
            pf_sn0 = srcS[e0];
            pf_av0 = (lane < 16) ? __ldcs(&attrS[(size_t)e0 * 16 + lane]) : 0.f;
        }
        if (e0 + 1 < e1) {
            pf_sn1 = srcS[e0 + 1];
            pf_av1 = (lane < 16) ? __ldcs(&attrS[(size_t)(e0 + 1) * 16 + lane]) : 0.f;
        }

        int e = e0;
        while (e + 1 < e1) {
            const int sn0 = pf_sn0, sn1 = pf_sn1;
            const float av0 = pf_av0, av1 = pf_av1;
            if (e + 2 < e1) {
                pf_sn0 = srcS[e + 2];
                pf_av0 = (lane < 16) ? __ldcs(&attrS[(size_t)(e + 2) * 16 + lane]) : 0.f;
            }
            if (e + 3 < e1) {
                pf_sn1 = srcS[e + 3];
                pf_av1 = (lane < 16) ? __ldcs(&attrS[(size_t)(e + 3) * 16 + lane]) : 0.f;
            }

            const uint2* kv0 = (const uint2*)(KV + (size_t)sn0 * (2 * C));
            const uint2* kv1 = (const uint2*)(KV + (size_t)sn1 * (2 * C));

            uint2 ku0[NV], vu0[NV], ku1[NV], vu1[NV];
            #pragma unroll
            for (int i = 0; i < NV; i++) {
                ku0[i] = kv0[lane + i * 32];
                vu0[i] = kv0[C / 4 + lane + i * 32];
                ku1[i] = kv1[lane + i * 32];
                vu1[i] = kv1[C / 4 + lane + i * 32];
            }

            float p0 = av0 * pP, p1 = av1 * pP;
            #pragma unroll
            for (int i = 0; i < NV; i++) {
                float2 a0 = __half22float2(*(const __half2*)&ku0[i].x);
                float2 b0 = __half22float2(*(const __half2*)&ku0[i].y);
                float2 a1 = __half22float2(*(const __half2*)&ku1[i].x);
                float2 b1 = __half22float2(*(const __half2*)&ku1[i].y);
                p0 += q[i].x * a0.x + q[i].y * a0.y + q[i].z * b0.x + q[i].w * b0.y;
                p1 += q[i].x * a1.x + q[i].y * a1.y + q[i].z * b1.x + q[i].w * b1.y;
            }
            #pragma unroll
            for (int o = 16; o; o >>= 1) {
                p0 += __shfl_xor_sync(0xFFFFFFFFu, p0, o);
                p1 += __shfl_xor_sync(0xFFFFFFFFu, p1, o);
            }

            const float w0 = __expf(p0 * isc);
            const float w1 = __expf(p1 * isc);
            s += w0 + w1;
            tacc += w0 * av0 + w1 * av1;
            #pragma unroll
            for (int i = 0; i < NV; i++) {
                float2 a0 = __half22float2(*(const __half2*)&vu0[i].x);
                float2 b0 = __half22float2(*(const __half2*)&vu0[i].y);
                float2 a1 = __half22float2(*(const __half2*)&vu1[i].x);
                float2 b1 = __half22float2(*(const __half2*)&vu1[i].y);
                vacc[i].x += w0 * a0.x + w1 * a1.x;
                vacc[i].y += w0 * a0.y + w1 * a1.y;
                vacc[i].z += w0 * b0.x + w1 * b1.x;
                vacc[i].w += w0 * b0.y + w1 * b1.y;
            }
            e += 2;
        }

        if (e < e1) {
            const int sn = pf_sn0;
            const float av = pf_av0;
            const uint2* kv = (const uint2*)(KV + (size_t)sn * (2 * C));
            uint2 ku[NV], vu[NV];
            #pragma unroll
            for (int i = 0; i < NV; i++) {
                ku[i] = kv[lane + i * 32];
                vu[i] = kv[C / 4 + lane + i * 32];
            }

            float part = av * pP;
            #pragma unroll
            for (int i = 0; i < NV; i++) {
                float2 a = __half22float2(*(const __half2*)&ku[i].x);
                float2 b = __half22float2(*(const __half2*)&ku[i].y);
                part += q[i].x * a.x + q[i].y * a.y + q[i].z * b.x + q[i].w * b.y;
            }
            #pragma unroll
            for (int o = 16; o; o >>= 1) part += __shfl_xor_sync(0xFFFFFFFFu, part, o);

            const float p = __expf(part * isc);
            s += p;
            tacc += p * av;
            #pragma unroll
            for (int i = 0; i < NV; i++) {
                float2 a = __half22float2(*(const __half2*)&vu[i].x);
                float2 b = __half22float2(*(const __half2*)&vu[i].y);
                vacc[i].x += p * a.x;
                vacc[i].y += p * a.y;
                vacc[i].z += p * b.x;
                vacc[i].w += p * b.y;
            }
        }

        const float inv = 1.f / (s + 1e-16f);

        float4 ed[NV];
        #pragma unroll
        for (int i = 0; i < NV; i++) ed[i] = make_float4(0.f, 0.f, 0.f, 0.f);
        #pragma unroll
        for (int f = 0; f < 16; f++) {
            const float tf = __shfl_sync(0xFFFFFFFFu, tacc, f) * inv;
            #pragma unroll
            for (int i = 0; i < NV; i++) {
                float4 w = *(const float4*)&Ws[f * C + (lane + i * 32) * 4];
                ed[i].x += tf * w.x; ed[i].y += tf * w.y;
                ed[i].z += tf * w.z; ed[i].w += tf * w.w;
            }
        }

        float4* hb = (float4*)(QKVS + (size_t)node * ld + 3 * C);
        #pragma unroll
        for (int i = 0; i < NV; i++) {
            float4 sk = hb[lane + i * 32];
            float4 o;
            o.x = sk.x + vacc[i].x * inv + ed[i].x;
            o.y = sk.y + vacc[i].y * inv + ed[i].y;
            o.z = sk.z + vacc[i].z * inv + ed[i].z;
            o.w = sk.w + vacc[i].w * inv + ed[i].w;
            if (RELU) {
                o.x = fmaxf(o.x, 0.f); o.y = fmaxf(o.y, 0.f);
                o.z = fmaxf(o.z, 0.f); o.w = fmaxf(o.w, 0.f);
            }
            hb[lane + i * 32] = o;
        }
    }
}

// ------------------------- classifier ----------------------------------------
__global__ __launch_bounds__(256) void classifier_k(
    const float* __restrict__ H, int ldh, const float* __restrict__ Wc,
    const float* __restrict__ bc, float* __restrict__ out, int M)
{
    __shared__ float Ws[256 * 10];
    for (int i = threadIdx.x; i < 2560; i += blockDim.x) Ws[i] = Wc[i];
    __syncthreads();

    int row  = blockIdx.x * 8 + (threadIdx.x >> 5);
    int lane = threadIdx.x & 31;
    if (row >= M) return;

    float acc[10];
    #pragma unroll
    for (int c = 0; c < 10; c++) acc[c] = 0.f;

    for (int k = lane; k < 256; k += 32) {
        float h = H[(size_t)row * ldh + k];
        #pragma unroll
        for (int c = 0; c < 10; c++) acc[c] += h * Ws[k * 10 + c];
    }
    #pragma unroll
    for (int c = 0; c < 10; c++)
        #pragma unroll
        for (int o = 16; o; o >>= 1)
            acc[c] += __shfl_xor_sync(0xFFFFFFFFu, acc[c], o);

    if (lane == 0) {
        #pragma unroll
        for (int c = 0; c < 10; c++)
            out[(size_t)row * 10 + c] = acc[c] + bc[c];
    }
}

// ------------------------- launch --------------------------------------------
extern "C" void kernel_launch(void* const* d_in, const int* in_sizes, int n_in,
                              void* d_out, int out_size)
{
    const float* x    = (const float*)d_in[0];
    const int*   ei   = (const int*)d_in[1];
    const float* attr = (const float*)d_in[2];
    const int* src = ei;
    const int* dst = ei + NE;

    float *B1, *B2, *Wp, *bp, *attrS;
    __half* KV;
    int *cnt, *off, *bsum, *cursor, *srcS;
    cudaGetSymbolAddress((void**)&B1,     g_B1);
    cudaGetSymbolAddress((void**)&B2,     g_B2);
    cudaGetSymbolAddress((void**)&KV,     g_KV);
    cudaGetSymbolAddress((void**)&Wp,     g_Wp);
    cudaGetSymbolAddress((void**)&bp,     g_bp);
    cudaGetSymbolAddress((void**)&cnt,    g_cnt);
    cudaGetSymbolAddress((void**)&off,    g_off);
    cudaGetSymbolAddress((void**)&bsum,   g_bsum);
    cudaGetSymbolAddress((void**)&cursor, g_cursor);
    cudaGetSymbolAddress((void**)&srcS,   g_srcS);
    cudaGetSymbolAddress((void**)&attrS,  g_attrS);

    auto IN = [&](int i) { return (const float*)d_in[i]; };

    static cudaStream_t sSide = nullptr;
    static cudaEvent_t  evFork = nullptr, evSide = nullptr;
    if (sSide == nullptr) {
        cudaStreamCreateWithFlags(&sSide, cudaStreamNonBlocking);
        cudaEventCreateWithFlags(&evFork, cudaEventDisableTiming);
        cudaEventCreateWithFlags(&evSide, cudaEventDisableTiming);
    }

    float* WpS[3] = { Wp, Wp + 147456, Wp + 294912 };
    float* bpS[3] = { bp, bp + 1280,   bp + 2560 };

    // ---- fork: side stream does edge sort + pack for layers 2,3 ----
    cudaEventRecord(evFork, 0);
    cudaStreamWaitEvent(sSide, evFork, 0);

    zero_cnt_k<<<(NN + 255) / 256, 256, 0, sSide>>>(cnt, NN);
    hist_k<<<(NE + 255) / 256, 256, 0, sSide>>>(dst, cnt, NE);
    scan1_k<<<SCAN_NB, SCAN_T, 0, sSide>>>(cnt, off, bsum, NN);
    scan2_k<<<1, 128, 0, sSide>>>(bsum, SCAN_NB);
    scan3_k<<<SCAN_NB, SCAN_T, 0, sSide>>>(off, bsum, cursor, NN, NE);
    scatter_k<<<(NE + 255) / 256, 256, 0, sSide>>>(src, dst, attr, cursor, srcS, attrS, NE);

    for (int l = 1; l < 3; l++) {
        const int base = 3 + l * 9;
        pack_k<<<256, 256, 0, sSide>>>(IN(base + 0), IN(base + 2), IN(base + 4),
                                       IN(base + 7), IN(base + 1), IN(base + 3),
                                       IN(base + 5), IN(base + 8), IN(base + 6),
                                       WpS[l], bpS[l], 128, l == 2 ? 256 : 128);
    }
    cudaEventRecord(evSide, sSide);

    // ---- main stream ----
    const float* Ain[3]  = { x, B1 + 3 * 128, B2 + 3 * 128 };
    int          lda[3]  = { 128, 640, 640 };
    int          Cc[3]   = { 128, 128, 256 };
    float*       outb[3] = { B1, B2, B1 };
    int          ldo[3]  = { 640, 640, 1152 };

    pack_k<<<256, 256>>>(IN(3), IN(5), IN(7), IN(10), IN(4), IN(6), IN(8), IN(11),
                         IN(9), WpS[0], bpS[0], 128, 128);

    bool joined = false;
    for (int l = 0; l < 3; l++) {
        const int C = Cc[l];
        float* out = outb[l];
        const int ld = ldo[l];

        dim3 gg((NN + 127) / 128, (4 * C + 128) / 128);
        sgemm_tc_k<<<gg, 256>>>(Ain[l], lda[l], WpS[l], 4 * C + 128, bpS[l],
                                out, ld, KV, C, NN, 128);

        if (!joined) {
            cudaStreamWaitEvent(0, evSide, 0);
            joined = true;
        }

        const float* We = IN(3 + l * 9 + 6);
        float isc = 1.0f / sqrtf((float)C);
        if (C == 128) {
            if (l < 2)
                fused_attn_k<128, true ><<<1536, 256>>>(out, ld, KV, attrS, srcS, off, We, isc, NN);
            else
                fused_attn_k<128, false><<<1536, 256>>>(out, ld, KV, attrS, srcS, off, We, isc, NN);
        } else {
            if (l < 2)
                fused_attn_k<256, true ><<<1536, 256>>>(out, ld, KV, attrS, srcS, off, We, isc, NN);
            else
                fused_attn_k<256, false><<<1536, 256>>>(out, ld, KV, attrS, srcS, off, We, isc, NN);
        }
    }

    classifier_k<<<(NN + 7) / 8, 256>>>(B1 + 768, 1152, IN(30), IN(31), (float*)d_out, NN);
}